// round 13
// baseline (speedup 1.0000x reference)
#include <cuda_runtime.h>
#include <math.h>
#include <stdint.h>

#define NPTS 8192
#define DIM  256
#define BM 128
#define BN 128
#define BKC 128           // k-columns per chunk (int8) = 128 bytes per row
#define NCHUNK 2          // 256 / 128

// dynamic smem (bytes): A0,A1,B0,B1 (16KB each) + aux
#define OFF_A0 0
#define OFF_A1 16384
#define OFF_B0 32768
#define OFF_B1 49152
#define OFF_AUX 65536     // c2s,s2s,rowP,colP,scC,scS : 6 x 128 f32
#define SMEM_TOTAL (65536 + 3072)

#define LN2F 0.6931471805599453f
#define LOG2EF 1.4426950408889634f

static __device__ int8_t g_Cb[NPTS * DIM];
static __device__ int8_t g_Sb[NPTS * DIM];
static __device__ float g_c2[NPTS], g_s2[NPTS];
static __device__ float g_scC[NPTS], g_scS[NPTS];
static __device__ float g_rowsum[NPTS], g_colsum[NPTS];

// ---------------------------------------------------------------------------
__device__ __forceinline__ uint32_t smem_u32(const void* p) {
    uint32_t a;
    asm("{.reg .u64 t; cvta.to.shared.u64 t, %1; cvt.u32.u64 %0, t;}" : "=r"(a) : "l"(p));
    return a;
}
__device__ __forceinline__ uint32_t swz(uint32_t x) { return x ^ ((x >> 3) & 0x70); }

__device__ __forceinline__ void cp16(uint32_t dst, const void* src) {
    asm volatile("cp.async.cg.shared.global [%0], [%1], 16;" :: "r"(dst), "l"(src));
}
__device__ __forceinline__ void ldsm4(uint32_t* r, uint32_t a) {
    asm volatile("ldmatrix.sync.aligned.m8n8.x4.shared.b16 {%0,%1,%2,%3}, [%4];"
                 : "=r"(r[0]), "=r"(r[1]), "=r"(r[2]), "=r"(r[3]) : "r"(a));
}
// s8 x s8 -> s32, m16n8k32
__device__ __forceinline__ void mma_s8(int32_t* d, const uint32_t* a, const uint32_t* b) {
    asm volatile(
        "mma.sync.aligned.m16n8k32.row.col.s32.s8.s8.s32 "
        "{%0,%1,%2,%3}, {%4,%5,%6,%7}, {%8,%9}, {%0,%1,%2,%3};\n"
        : "+r"(d[0]), "+r"(d[1]), "+r"(d[2]), "+r"(d[3])
        : "r"(a[0]), "r"(a[1]), "r"(a[2]), "r"(a[3]), "r"(b[0]), "r"(b[1]));
}
__device__ __forceinline__ int8_t q8(float x, float inv) {
    int v = __float2int_rn(x * inv);
    return (int8_t)v;   // |x*inv| <= 127 by construction
}

// ---------------------------------------------------------------------------
// Prepass: per-row int8 quantization, norms of the QUANTIZED vectors, zeroing.
// One warp per row (handles C and S). grid = NPTS/8, block = 256.
// ---------------------------------------------------------------------------
__global__ void dcl_prep_kernel(const float* __restrict__ C,
                                const float* __restrict__ S,
                                float* __restrict__ out) {
    int warp = threadIdx.x >> 5;
    int lane = threadIdx.x & 31;
    int row  = blockIdx.x * 8 + warp;

    if (lane == 0) { g_rowsum[row] = 0.0f; g_colsum[row] = 0.0f; }
    if (blockIdx.x == 0 && threadIdx.x == 0) out[0] = 0.0f;

    {
        const float4* src = (const float4*)(C + (size_t)row * DIM);
        float4 v0 = src[lane * 2], v1 = src[lane * 2 + 1];
        float mx = fmaxf(fmaxf(fmaxf(fabsf(v0.x), fabsf(v0.y)), fmaxf(fabsf(v0.z), fabsf(v0.w))),
                         fmaxf(fmaxf(fabsf(v1.x), fabsf(v1.y)), fmaxf(fabsf(v1.z), fabsf(v1.w))));
#pragma unroll
        for (int m = 16; m >= 1; m >>= 1)
            mx = fmaxf(mx, __shfl_xor_sync(0xffffffffu, mx, m));
        float inv = 127.0f / mx;
        int q[8];
        q[0] = __float2int_rn(v0.x * inv); q[1] = __float2int_rn(v0.y * inv);
        q[2] = __float2int_rn(v0.z * inv); q[3] = __float2int_rn(v0.w * inv);
        q[4] = __float2int_rn(v1.x * inv); q[5] = __float2int_rn(v1.y * inv);
        q[6] = __float2int_rn(v1.z * inv); q[7] = __float2int_rn(v1.w * inv);
        uint2 pk;
        pk.x = (uint32_t)(q[0] & 0xFF) | ((uint32_t)(q[1] & 0xFF) << 8) |
               ((uint32_t)(q[2] & 0xFF) << 16) | ((uint32_t)(q[3] & 0xFF) << 24);
        pk.y = (uint32_t)(q[4] & 0xFF) | ((uint32_t)(q[5] & 0xFF) << 8) |
               ((uint32_t)(q[6] & 0xFF) << 16) | ((uint32_t)(q[7] & 0xFF) << 24);
        ((uint2*)(g_Cb + (size_t)row * DIM))[lane] = pk;
        float qq = 0.0f;
#pragma unroll
        for (int i = 0; i < 8; i++) qq += (float)(q[i] * q[i]);
#pragma unroll
        for (int m = 16; m >= 1; m >>= 1) qq += __shfl_xor_sync(0xffffffffu, qq, m);
        float sc = mx * (1.0f / 127.0f);
        if (lane == 0) { g_scC[row] = sc; g_c2[row] = sc * sc * qq; }
    }
    {
        const float4* src = (const float4*)(S + (size_t)row * DIM);
        float4 v0 = src[lane * 2], v1 = src[lane * 2 + 1];
        float mx = fmaxf(fmaxf(fmaxf(fabsf(v0.x), fabsf(v0.y)), fmaxf(fabsf(v0.z), fabsf(v0.w))),
                         fmaxf(fmaxf(fabsf(v1.x), fabsf(v1.y)), fmaxf(fabsf(v1.z), fabsf(v1.w))));
#pragma unroll
        for (int m = 16; m >= 1; m >>= 1)
            mx = fmaxf(mx, __shfl_xor_sync(0xffffffffu, mx, m));
        float inv = 127.0f / mx;
        int q[8];
        q[0] = __float2int_rn(v0.x * inv); q[1] = __float2int_rn(v0.y * inv);
        q[2] = __float2int_rn(v0.z * inv); q[3] = __float2int_rn(v0.w * inv);
        q[4] = __float2int_rn(v1.x * inv); q[5] = __float2int_rn(v1.y * inv);
        q[6] = __float2int_rn(v1.z * inv); q[7] = __float2int_rn(v1.w * inv);
        uint2 pk;
        pk.x = (uint32_t)(q[0] & 0xFF) | ((uint32_t)(q[1] & 0xFF) << 8) |
               ((uint32_t)(q[2] & 0xFF) << 16) | ((uint32_t)(q[3] & 0xFF) << 24);
        pk.y = (uint32_t)(q[4] & 0xFF) | ((uint32_t)(q[5] & 0xFF) << 8) |
               ((uint32_t)(q[6] & 0xFF) << 16) | ((uint32_t)(q[7] & 0xFF) << 24);
        ((uint2*)(g_Sb + (size_t)row * DIM))[lane] = pk;
        float qq = 0.0f;
#pragma unroll
        for (int i = 0; i < 8; i++) qq += (float)(q[i] * q[i]);
#pragma unroll
        for (int m = 16; m >= 1; m >>= 1) qq += __shfl_xor_sync(0xffffffffu, qq, m);
        float sc = mx * (1.0f / 127.0f);
        if (lane == 0) { g_scS[row] = sc; g_s2[row] = sc * sc * qq; }
    }
}

// ---------------------------------------------------------------------------
// Main: s8 m16n8k32 IMMA GEMM (128x128 tile, K=256 in 2 chunks) + fused epilogue
// ---------------------------------------------------------------------------
__global__ __launch_bounds__(256, 2)
void dcl_main_kernel(const float* __restrict__ T, float* __restrict__ out) {
    extern __shared__ char smem[];
    const uint32_t sb = smem_u32(smem);

    const int tid   = threadIdx.x;
    const int lane  = tid & 31;
    const int warp  = tid >> 5;
    const int warpM = warp & 1;        // 2 warps along M (64 rows)
    const int warpN = warp >> 1;       // 4 warps along N (32 cols)
    const int rowBase = blockIdx.y * BM;
    const int colBase = blockIdx.x * BN;

    const int mrow  = lane & 7;
    const int matLo = (lane >> 3) & 1;
    const int matHi = (lane >> 4) & 1;

    float* aux  = (float*)(smem + OFF_AUX);
    float* c2s  = aux;
    float* s2s  = aux + 128;
    float* rowP = aux + 256;
    float* colP = aux + 384;
    float* scCs = aux + 512;
    float* scSs = aux + 640;
    if (tid < 128) {
        c2s[tid] = g_c2[rowBase + tid];
        s2s[tid] = g_s2[colBase + tid];
        scCs[tid] = g_scC[rowBase + tid];
        scSs[tid] = g_scS[colBase + tid];
        rowP[tid] = 0.0f;
        colP[tid] = 0.0f;
    }

    const uint32_t aB[2] = { sb + OFF_A0, sb + OFF_A1 };
    const uint32_t bB[2] = { sb + OFF_B0, sb + OFF_B1 };

    int32_t acc[4][4][4];
#pragma unroll
    for (int mi = 0; mi < 4; mi++)
#pragma unroll
        for (int ni = 0; ni < 4; ni++)
#pragma unroll
            for (int c = 0; c < 4; c++) acc[mi][ni][c] = 0;

    auto fill = [&](int buf, int ch) {
#pragma unroll
        for (int t = 0; t < 4; t++) {
            int idx = tid + t * 256;
            int r = idx >> 3, g = idx & 7;
            cp16(aB[buf] + swz((uint32_t)(r * 128 + g * 16)),
                 g_Cb + (size_t)(rowBase + r) * DIM + ch * BKC + g * 16);
        }
#pragma unroll
        for (int t = 0; t < 4; t++) {
            int idx = tid + t * 256;
            int r = idx >> 3, g = idx & 7;
            cp16(bB[buf] + swz((uint32_t)(r * 128 + g * 16)),
                 g_Sb + (size_t)(colBase + r) * DIM + ch * BKC + g * 16);
        }
        asm volatile("cp.async.commit_group;" ::: "memory");
    };

    fill(0, 0);
    fill(1, 1);

    const uint32_t aRowOff = (uint32_t)(warpM * 64 + matLo * 8 + mrow) * 128;
    const uint32_t bRowOff = (uint32_t)(warpN * 32 + matHi * 8 + mrow) * 128;

    uint32_t a[2][4][4], b[2][4][2];

    auto ldfrag = [&](int slot, uint32_t ab, uint32_t bb, int ks) {
        const uint32_t ca = (uint32_t)((((ks << 1) | matHi) ^ mrow) << 4);
        const uint32_t cb = (uint32_t)((((ks << 1) | matLo) ^ mrow) << 4);
#pragma unroll
        for (int mi = 0; mi < 4; mi++)
            ldsm4(a[slot][mi], ab + mi * 2048 + ca);
#pragma unroll
        for (int p = 0; p < 2; p++) {
            uint32_t r[4];
            ldsm4(r, bb + p * 2048 + cb);
            b[slot][2 * p][0] = r[0]; b[slot][2 * p][1] = r[1];
            b[slot][2 * p + 1][0] = r[2]; b[slot][2 * p + 1][1] = r[3];
        }
    };

#pragma unroll
    for (int ch = 0; ch < NCHUNK; ch++) {
        if (ch < NCHUNK - 1) asm volatile("cp.async.wait_group 1;" ::: "memory");
        else                 asm volatile("cp.async.wait_group 0;" ::: "memory");
        __syncthreads();

        const uint32_t ab = aB[ch] + aRowOff;
        const uint32_t bb = bB[ch] + bRowOff;

        ldfrag(0, ab, bb, 0);
#pragma unroll
        for (int ks = 0; ks < 4; ks++) {       // 4 k32-steps per 128-col chunk
            const int cur = ks & 1;
            if (ks < 3) ldfrag(cur ^ 1, ab, bb, ks + 1);
#pragma unroll
            for (int mi = 0; mi < 4; mi++)
#pragma unroll
                for (int ni = 0; ni < 4; ni++)
                    mma_s8(acc[mi][ni], a[cur][mi], b[cur][ni]);
        }
    }

    // ---------------- epilogue ----------------
    __syncthreads();

    const float kk = -__expf(T[0]) * LOG2EF;   // e = ex2(dist * kk)
    const bool diagCTA = (blockIdx.x == blockIdx.y);
    const int g   = lane >> 2;
    const int tig = lane & 3;

    // per-thread row/col metadata
    float rsc[8], rb[8], csc[8], cb2[8];
#pragma unroll
    for (int i = 0; i < 8; i++) {
        int mi = i >> 1, h = i & 1;
        int rl = warpM * 64 + mi * 16 + g + h * 8;
        rsc[i] = -2.0f * scCs[rl];
        rb[i]  = c2s[rl];
    }
#pragma unroll
    for (int j = 0; j < 8; j++) {
        int ni = j >> 1, bb2 = j & 1;
        int cl = warpN * 32 + ni * 8 + tig * 2 + bb2;
        csc[j] = scSs[cl];
        cb2[j] = s2s[cl];
    }

    float rAcc[8], cAcc[8];
#pragma unroll
    for (int i = 0; i < 8; i++) { rAcc[i] = 0.0f; cAcc[i] = 0.0f; }
    float dloc = 0.0f;

#pragma unroll
    for (int mi = 0; mi < 4; mi++) {
#pragma unroll
        for (int ni = 0; ni < 4; ni++) {
#pragma unroll
            for (int c = 0; c < 4; c++) {
                const int h   = c >> 1;
                const int bb2 = c & 1;
                const int i = mi * 2 + h;
                const int j = ni * 2 + bb2;
                float fdot = (float)acc[mi][ni][c];
                float d2 = fmaxf(fmaf(rsc[i] * csc[j], fdot, rb[i] + cb2[j]), 0.0f);
                float dist;
                asm("sqrt.approx.f32 %0, %1;" : "=f"(dist) : "f"(d2));
                float f = dist * kk;
                float e;
                asm("ex2.approx.f32 %0, %1;" : "=f"(e) : "f"(f));
                rAcc[i] += e;
                cAcc[j] += e;
                if (diagCTA) {
                    const int rl = warpM * 64 + mi * 16 + g + h * 8;
                    const int cl = warpN * 32 + ni * 8 + tig * 2 + bb2;
                    if (rl == cl) dloc += f;
                }
            }
        }
    }

#pragma unroll
    for (int i = 0; i < 8; i++) {
        float v = rAcc[i];
        v += __shfl_xor_sync(0xffffffffu, v, 1);
        v += __shfl_xor_sync(0xffffffffu, v, 2);
        if (tig == 0) {
            int mi = i >> 1, h = i & 1;
            atomicAdd(&rowP[warpM * 64 + mi * 16 + h * 8 + g], v);
        }
    }
#pragma unroll
    for (int i = 0; i < 8; i++) {
        float v = cAcc[i];
        v += __shfl_xor_sync(0xffffffffu, v, 4);
        v += __shfl_xor_sync(0xffffffffu, v, 8);
        v += __shfl_xor_sync(0xffffffffu, v, 16);
        if (g == 0) {
            int ni = i >> 1, bb2 = i & 1;
            atomicAdd(&colP[warpN * 32 + ni * 8 + tig * 2 + bb2], v);
        }
    }

    if (diagCTA) {
#pragma unroll
        for (int m = 16; m >= 1; m >>= 1)
            dloc += __shfl_xor_sync(0xffffffffu, dloc, m);
        if (lane == 0) atomicAdd(out, -dloc * (LN2F / (float)NPTS));
    }

    __syncthreads();
    if (tid < 128) {
        atomicAdd(&g_rowsum[rowBase + tid], rowP[tid]);
        atomicAdd(&g_colsum[colBase + tid], colP[tid]);
    }
}

// ---------------------------------------------------------------------------
__global__ void dcl_final_kernel(float* __restrict__ out) {
    int i = blockIdx.x * blockDim.x + threadIdx.x;
    float v = logf(g_rowsum[i]) + logf(g_colsum[i]);
#pragma unroll
    for (int m = 16; m >= 1; m >>= 1) v += __shfl_xor_sync(0xffffffffu, v, m);
    if ((threadIdx.x & 31) == 0)
        atomicAdd(out, v * (0.5f / (float)NPTS));
}

// ---------------------------------------------------------------------------
extern "C" void kernel_launch(void* const* d_in, const int* in_sizes, int n_in,
                              void* d_out, int out_size) {
    const float* C = (const float*)d_in[0];
    const float* S = (const float*)d_in[1];
    const float* T = (const float*)d_in[2];
    float* out = (float*)d_out;

    static bool attr_set = false;
    if (!attr_set) {
        cudaFuncSetAttribute(dcl_main_kernel,
                             cudaFuncAttributeMaxDynamicSharedMemorySize, SMEM_TOTAL);
        attr_set = true;
    }

    dcl_prep_kernel<<<NPTS / 8, 256>>>(C, S, out);
    dim3 grid(NPTS / BN, NPTS / BM);
    dcl_main_kernel<<<grid, 256, SMEM_TOTAL>>>(T, out);
    dcl_final_kernel<<<NPTS / 1024, 1024>>>(out);
}

// round 14
// speedup vs baseline: 1.5109x; 1.5109x over previous
#include <cuda_runtime.h>
#include <cuda_fp16.h>
#include <math.h>
#include <stdint.h>

#define NPTS 8192
#define DIM  256
#define BM 128
#define BN 256
#define BKC 64            // k-columns per chunk (f16), 128B rows
#define NCHUNK 4          // 256 / 64

// dynamic smem (bytes): A0,A1 (16KB), B0,B1 (32KB) + aux
#define OFF_A0 0
#define OFF_A1 16384
#define OFF_B0 32768
#define OFF_B1 65536
#define OFF_AUX 98304     // c2s[128], s2s[256], rowP[128], colP[256]
#define SMEM_TOTAL (98304 + 3072)

#define LN2F 0.6931471805599453f
#define LOG2EF 1.4426950408889634f

static __device__ __half g_Cb[NPTS * DIM];
static __device__ __half g_Sb[NPTS * DIM];
static __device__ float g_c2[NPTS], g_s2[NPTS];
static __device__ float g_rowsum[NPTS], g_colsum[NPTS];

// ---------------------------------------------------------------------------
__device__ __forceinline__ uint32_t smem_u32(const void* p) {
    uint32_t a;
    asm("{.reg .u64 t; cvta.to.shared.u64 t, %1; cvt.u32.u64 %0, t;}" : "=r"(a) : "l"(p));
    return a;
}
__device__ __forceinline__ uint32_t swz(uint32_t x) { return x ^ ((x >> 3) & 0x70); }

__device__ __forceinline__ void cp16(uint32_t dst, const void* src) {
    asm volatile("cp.async.cg.shared.global [%0], [%1], 16;" :: "r"(dst), "l"(src));
}
__device__ __forceinline__ void ldsm4(uint32_t* r, uint32_t a) {
    asm volatile("ldmatrix.sync.aligned.m8n8.x4.shared.b16 {%0,%1,%2,%3}, [%4];"
                 : "=r"(r[0]), "=r"(r[1]), "=r"(r[2]), "=r"(r[3]) : "r"(a));
}
// f16 inputs, f16 accumulator
__device__ __forceinline__ void mma_f16(uint32_t* d, const uint32_t* a, const uint32_t* b) {
    asm volatile(
        "mma.sync.aligned.m16n8k16.row.col.f16.f16.f16.f16 "
        "{%0,%1}, {%2,%3,%4,%5}, {%6,%7}, {%0,%1};\n"
        : "+r"(d[0]), "+r"(d[1])
        : "r"(a[0]), "r"(a[1]), "r"(a[2]), "r"(a[3]), "r"(b[0]), "r"(b[1]));
}

// ---------------------------------------------------------------------------
// Prepass: f32 -> f16 copies, norms from the ROUNDED values, zero accums.
// One warp per row (handles C and S). grid = NPTS/8, block = 256.
// ---------------------------------------------------------------------------
__global__ void dcl_prep_kernel(const float* __restrict__ C,
                                const float* __restrict__ S,
                                float* __restrict__ out) {
    int warp = threadIdx.x >> 5;
    int lane = threadIdx.x & 31;
    int row  = blockIdx.x * 8 + warp;

    if (lane == 0) { g_rowsum[row] = 0.0f; g_colsum[row] = 0.0f; }
    if (blockIdx.x == 0 && threadIdx.x == 0) out[0] = 0.0f;

    {
        const float4* src = (const float4*)(C + (size_t)row * DIM);
        float4 v0 = src[lane * 2], v1 = src[lane * 2 + 1];
        __half2 h0 = __floats2half2_rn(v0.x, v0.y), h1 = __floats2half2_rn(v0.z, v0.w);
        __half2 h2 = __floats2half2_rn(v1.x, v1.y), h3 = __floats2half2_rn(v1.z, v1.w);
        uint4 pk = make_uint4(*(uint32_t*)&h0, *(uint32_t*)&h1,
                              *(uint32_t*)&h2, *(uint32_t*)&h3);
        ((uint4*)(g_Cb + (size_t)row * DIM))[lane] = pk;
        float2 a = __half22float2(h0), b = __half22float2(h1);
        float2 c = __half22float2(h2), d = __half22float2(h3);
        float ss = a.x * a.x + a.y * a.y + b.x * b.x + b.y * b.y
                 + c.x * c.x + c.y * c.y + d.x * d.x + d.y * d.y;
#pragma unroll
        for (int m = 16; m >= 1; m >>= 1) ss += __shfl_xor_sync(0xffffffffu, ss, m);
        if (lane == 0) g_c2[row] = ss;
    }
    {
        const float4* src = (const float4*)(S + (size_t)row * DIM);
        float4 v0 = src[lane * 2], v1 = src[lane * 2 + 1];
        __half2 h0 = __floats2half2_rn(v0.x, v0.y), h1 = __floats2half2_rn(v0.z, v0.w);
        __half2 h2 = __floats2half2_rn(v1.x, v1.y), h3 = __floats2half2_rn(v1.z, v1.w);
        uint4 pk = make_uint4(*(uint32_t*)&h0, *(uint32_t*)&h1,
                              *(uint32_t*)&h2, *(uint32_t*)&h3);
        ((uint4*)(g_Sb + (size_t)row * DIM))[lane] = pk;
        float2 a = __half22float2(h0), b = __half22float2(h1);
        float2 c = __half22float2(h2), d = __half22float2(h3);
        float ss = a.x * a.x + a.y * a.y + b.x * b.x + b.y * b.y
                 + c.x * c.x + c.y * c.y + d.x * d.x + d.y * d.y;
#pragma unroll
        for (int m = 16; m >= 1; m >>= 1) ss += __shfl_xor_sync(0xffffffffu, ss, m);
        if (lane == 0) g_s2[row] = ss;
    }
}

// ---------------------------------------------------------------------------
// Main: f16 m16n8k16 GEMM, 128x256 CTA tile (64x64 warp tile), f16 accum
// ---------------------------------------------------------------------------
__global__ __launch_bounds__(256, 2)
void dcl_main_kernel(const float* __restrict__ T, float* __restrict__ out) {
    extern __shared__ char smem[];
    const uint32_t sb = smem_u32(smem);

    const int tid   = threadIdx.x;
    const int lane  = tid & 31;
    const int warp  = tid >> 5;
    const int warpM = warp & 1;        // 2 warps along M (64 rows)
    const int warpN = warp >> 1;       // 4 warps along N (64 cols each)
    const int rowBase = blockIdx.y * BM;
    const int colBase = blockIdx.x * BN;

    const int mrow  = lane & 7;
    const int matLo = (lane >> 3) & 1;
    const int matHi = (lane >> 4) & 1;

    float* aux  = (float*)(smem + OFF_AUX);
    float* c2s  = aux;            // 128
    float* s2s  = aux + 128;      // 256
    float* rowP = aux + 384;      // 128
    float* colP = aux + 512;      // 256
    if (tid < 128) {
        c2s[tid] = g_c2[rowBase + tid];
        rowP[tid] = 0.0f;
    }
    s2s[tid] = g_s2[colBase + tid];
    colP[tid] = 0.0f;

    const uint32_t aB[2] = { sb + OFF_A0, sb + OFF_A1 };
    const uint32_t bB[2] = { sb + OFF_B0, sb + OFF_B1 };

    uint32_t acc[4][8][2];   // f16x2 accumulators: mi x ni x {rowg, rowg+8}
#pragma unroll
    for (int mi = 0; mi < 4; mi++)
#pragma unroll
        for (int ni = 0; ni < 8; ni++) { acc[mi][ni][0] = 0u; acc[mi][ni][1] = 0u; }

    auto fill = [&](int buf, int ch) {
#pragma unroll
        for (int t = 0; t < 4; t++) {
            int idx = tid + t * 256;
            int r = idx >> 3, g = idx & 7;
            cp16(aB[buf] + swz((uint32_t)(r * 128 + g * 16)),
                 g_Cb + (size_t)(rowBase + r) * DIM + ch * BKC + g * 8);
        }
#pragma unroll
        for (int t = 0; t < 8; t++) {
            int idx = tid + t * 256;
            int r = idx >> 3, g = idx & 7;
            cp16(bB[buf] + swz((uint32_t)(r * 128 + g * 16)),
                 g_Sb + (size_t)(colBase + r) * DIM + ch * BKC + g * 8);
        }
        asm volatile("cp.async.commit_group;" ::: "memory");
    };

    fill(0, 0);
    fill(1, 1);

    const uint32_t aRowOff = (uint32_t)(warpM * 64 + matLo * 8 + mrow) * 128;
    const uint32_t bRowOff = (uint32_t)(warpN * 64 + matHi * 8 + mrow) * 128;

#pragma unroll
    for (int ch = 0; ch < NCHUNK; ch++) {
        if (ch < NCHUNK - 1) asm volatile("cp.async.wait_group 1;" ::: "memory");
        else                 asm volatile("cp.async.wait_group 0;" ::: "memory");
        __syncthreads();

        const uint32_t ab = aB[ch & 1] + aRowOff;
        const uint32_t bb = bB[ch & 1] + bRowOff;

#pragma unroll
        for (int ks = 0; ks < 4; ks++) {
            const uint32_t ca = (uint32_t)((((ks << 1) | matHi) ^ mrow) << 4);
            const uint32_t cb = (uint32_t)((((ks << 1) | matLo) ^ mrow) << 4);
            uint32_t a[4][4], b[8][2];
#pragma unroll
            for (int mi = 0; mi < 4; mi++)
                ldsm4(a[mi], ab + mi * 2048 + ca);
#pragma unroll
            for (int p = 0; p < 4; p++) {
                uint32_t r[4];
                ldsm4(r, bb + p * 2048 + cb);
                b[2 * p][0] = r[0]; b[2 * p][1] = r[1];
                b[2 * p + 1][0] = r[2]; b[2 * p + 1][1] = r[3];
            }
#pragma unroll
            for (int mi = 0; mi < 4; mi++)
#pragma unroll
                for (int ni = 0; ni < 8; ni++)
                    mma_f16(acc[mi][ni], a[mi], b[ni]);
        }

        if (ch + 2 < NCHUNK) {
            __syncthreads();          // all warps done reading buf (ch&1)
            fill(ch & 1, ch + 2);
        }
    }

    // ---------------- epilogue ----------------
    __syncthreads();

    const float kk = -__expf(T[0]) * LOG2EF;   // e = ex2(dist * kk)
    const bool diagCTA = (rowBase >= colBase) && (rowBase < colBase + BN);
    const int g   = lane >> 2;
    const int tig = lane & 3;

    float rAcc[8], cAcc[16];
#pragma unroll
    for (int i = 0; i < 8; i++) rAcc[i] = 0.0f;
#pragma unroll
    for (int j = 0; j < 16; j++) cAcc[j] = 0.0f;
    float dloc = 0.0f;

#pragma unroll
    for (int mi = 0; mi < 4; mi++) {
#pragma unroll
        for (int ni = 0; ni < 8; ni++) {
            float2 f01 = __half22float2(*(__half2*)&acc[mi][ni][0]); // row g,   cols 2tig..+1
            float2 f23 = __half22float2(*(__half2*)&acc[mi][ni][1]); // row g+8, cols 2tig..+1
            float accf[4] = { f01.x, f01.y, f23.x, f23.y };
#pragma unroll
            for (int c = 0; c < 4; c++) {
                const int h   = c >> 1;
                const int bb2 = c & 1;
                const int rl = warpM * 64 + mi * 16 + g + h * 8;
                const int cl = warpN * 64 + ni * 8 + tig * 2 + bb2;
                float d2 = fmaxf(fmaf(-2.0f, accf[c], c2s[rl] + s2s[cl]), 0.0f);
                float dist;
                asm("sqrt.approx.f32 %0, %1;" : "=f"(dist) : "f"(d2));
                float f = dist * kk;
                float e;
                asm("ex2.approx.f32 %0, %1;" : "=f"(e) : "f"(f));
                rAcc[mi * 2 + h] += e;
                cAcc[ni * 2 + bb2] += e;
                if (diagCTA && (rowBase + rl) == (colBase + cl)) dloc += f;
            }
        }
    }

#pragma unroll
    for (int i = 0; i < 8; i++) {
        float v = rAcc[i];
        v += __shfl_xor_sync(0xffffffffu, v, 1);
        v += __shfl_xor_sync(0xffffffffu, v, 2);
        if (tig == 0) {
            int mi = i >> 1, h = i & 1;
            atomicAdd(&rowP[warpM * 64 + mi * 16 + h * 8 + g], v);
        }
    }
#pragma unroll
    for (int j = 0; j < 16; j++) {
        float v = cAcc[j];
        v += __shfl_xor_sync(0xffffffffu, v, 4);
        v += __shfl_xor_sync(0xffffffffu, v, 8);
        v += __shfl_xor_sync(0xffffffffu, v, 16);
        if (g == 0) {
            int ni = j >> 1, bb2 = j & 1;
            atomicAdd(&colP[warpN * 64 + ni * 8 + tig * 2 + bb2], v);
        }
    }

    if (diagCTA) {
#pragma unroll
        for (int m = 16; m >= 1; m >>= 1)
            dloc += __shfl_xor_sync(0xffffffffu, dloc, m);
        if (lane == 0) atomicAdd(out, -dloc * (LN2F / (float)NPTS));
    }

    __syncthreads();
    if (tid < 128) atomicAdd(&g_rowsum[rowBase + tid], rowP[tid]);
    atomicAdd(&g_colsum[colBase + tid], colP[tid]);
}

// ---------------------------------------------------------------------------
__global__ void dcl_final_kernel(float* __restrict__ out) {
    int i = blockIdx.x * blockDim.x + threadIdx.x;
    float v = logf(g_rowsum[i]) + logf(g_colsum[i]);
#pragma unroll
    for (int m = 16; m >= 1; m >>= 1) v += __shfl_xor_sync(0xffffffffu, v, m);
    if ((threadIdx.x & 31) == 0)
        atomicAdd(out, v * (0.5f / (float)NPTS));
}

// ---------------------------------------------------------------------------
extern "C" void kernel_launch(void* const* d_in, const int* in_sizes, int n_in,
                              void* d_out, int out_size) {
    const float* C = (const float*)d_in[0];
    const float* S = (const float*)d_in[1];
    const float* T = (const float*)d_in[2];
    float* out = (float*)d_out;

    static bool attr_set = false;
    if (!attr_set) {
        cudaFuncSetAttribute(dcl_main_kernel,
                             cudaFuncAttributeMaxDynamicSharedMemorySize, SMEM_TOTAL);
        attr_set = true;
    }

    dcl_prep_kernel<<<NPTS / 8, 256>>>(C, S, out);
    dim3 grid(NPTS / BN, NPTS / BM);
    dcl_main_kernel<<<grid, 256, SMEM_TOTAL>>>(T, out);
    dcl_final_kernel<<<NPTS / 1024, 1024>>>(out);
}

// round 15
// speedup vs baseline: 2.2914x; 1.5165x over previous
#include <cuda_runtime.h>
#include <cuda_fp16.h>
#include <math.h>
#include <stdint.h>

#define NPTS 8192
#define DIM  256
#define BM 128
#define BN 128
#define BKC 64            // k-columns per chunk (f16), 128B rows
#define NCHUNK 4          // 256 / 64

// dynamic smem (bytes): A0,A1,B0,B1 (16KB each) + aux
#define OFF_A0 0
#define OFF_A1 16384
#define OFF_B0 32768
#define OFF_B1 49152
#define OFF_AUX 65536     // c2s[128], s2s[128], rowP[128], colP[128]
#define SMEM_TOTAL (65536 + 2048)

#define LN2F 0.6931471805599453f
#define LOG2EF 1.4426950408889634f

static __device__ __half g_Cb[NPTS * DIM];
static __device__ __half g_Sb[NPTS * DIM];
static __device__ float g_c2[NPTS], g_s2[NPTS];
static __device__ float g_rowsum[NPTS], g_colsum[NPTS];

// ---------------------------------------------------------------------------
__device__ __forceinline__ uint32_t smem_u32(const void* p) {
    uint32_t a;
    asm("{.reg .u64 t; cvta.to.shared.u64 t, %1; cvt.u32.u64 %0, t;}" : "=r"(a) : "l"(p));
    return a;
}
__device__ __forceinline__ uint32_t swz(uint32_t x) { return x ^ ((x >> 3) & 0x70); }

__device__ __forceinline__ void cp16(uint32_t dst, const void* src) {
    asm volatile("cp.async.cg.shared.global [%0], [%1], 16;" :: "r"(dst), "l"(src));
}
__device__ __forceinline__ void ldsm4(uint32_t* r, uint32_t a) {
    asm volatile("ldmatrix.sync.aligned.m8n8.x4.shared.b16 {%0,%1,%2,%3}, [%4];"
                 : "=r"(r[0]), "=r"(r[1]), "=r"(r[2]), "=r"(r[3]) : "r"(a));
}
// f16 inputs, f16 accumulator
__device__ __forceinline__ void mma_f16(uint32_t* d, const uint32_t* a, const uint32_t* b) {
    asm volatile(
        "mma.sync.aligned.m16n8k16.row.col.f16.f16.f16.f16 "
        "{%0,%1}, {%2,%3,%4,%5}, {%6,%7}, {%0,%1};\n"
        : "+r"(d[0]), "+r"(d[1])
        : "r"(a[0]), "r"(a[1]), "r"(a[2]), "r"(a[3]), "r"(b[0]), "r"(b[1]));
}

// ---------------------------------------------------------------------------
// Prepass: f32 -> f16 copies, norms from the ROUNDED values, zero accums.
// One warp per row (handles C and S). grid = NPTS/8, block = 256.
// ---------------------------------------------------------------------------
__global__ void dcl_prep_kernel(const float* __restrict__ C,
                                const float* __restrict__ S,
                                float* __restrict__ out) {
    int warp = threadIdx.x >> 5;
    int lane = threadIdx.x & 31;
    int row  = blockIdx.x * 8 + warp;

    if (lane == 0) { g_rowsum[row] = 0.0f; g_colsum[row] = 0.0f; }
    if (blockIdx.x == 0 && threadIdx.x == 0) out[0] = 0.0f;

    {
        const float4* src = (const float4*)(C + (size_t)row * DIM);
        float4 v0 = src[lane * 2], v1 = src[lane * 2 + 1];
        __half2 h0 = __floats2half2_rn(v0.x, v0.y), h1 = __floats2half2_rn(v0.z, v0.w);
        __half2 h2 = __floats2half2_rn(v1.x, v1.y), h3 = __floats2half2_rn(v1.z, v1.w);
        uint4 pk = make_uint4(*(uint32_t*)&h0, *(uint32_t*)&h1,
                              *(uint32_t*)&h2, *(uint32_t*)&h3);
        ((uint4*)(g_Cb + (size_t)row * DIM))[lane] = pk;
        float2 a = __half22float2(h0), b = __half22float2(h1);
        float2 c = __half22float2(h2), d = __half22float2(h3);
        float ss = a.x * a.x + a.y * a.y + b.x * b.x + b.y * b.y
                 + c.x * c.x + c.y * c.y + d.x * d.x + d.y * d.y;
#pragma unroll
        for (int m = 16; m >= 1; m >>= 1) ss += __shfl_xor_sync(0xffffffffu, ss, m);
        if (lane == 0) g_c2[row] = ss;
    }
    {
        const float4* src = (const float4*)(S + (size_t)row * DIM);
        float4 v0 = src[lane * 2], v1 = src[lane * 2 + 1];
        __half2 h0 = __floats2half2_rn(v0.x, v0.y), h1 = __floats2half2_rn(v0.z, v0.w);
        __half2 h2 = __floats2half2_rn(v1.x, v1.y), h3 = __floats2half2_rn(v1.z, v1.w);
        uint4 pk = make_uint4(*(uint32_t*)&h0, *(uint32_t*)&h1,
                              *(uint32_t*)&h2, *(uint32_t*)&h3);
        ((uint4*)(g_Sb + (size_t)row * DIM))[lane] = pk;
        float2 a = __half22float2(h0), b = __half22float2(h1);
        float2 c = __half22float2(h2), d = __half22float2(h3);
        float ss = a.x * a.x + a.y * a.y + b.x * b.x + b.y * b.y
                 + c.x * c.x + c.y * c.y + d.x * d.x + d.y * d.y;
#pragma unroll
        for (int m = 16; m >= 1; m >>= 1) ss += __shfl_xor_sync(0xffffffffu, ss, m);
        if (lane == 0) g_s2[row] = ss;
    }
}

// ---------------------------------------------------------------------------
// Main: f16 m16n8k16 GEMM, f16 accumulators, 3 CTAs/SM, fused epilogue
// ---------------------------------------------------------------------------
__global__ __launch_bounds__(256, 3)
void dcl_main_kernel(const float* __restrict__ T, float* __restrict__ out) {
    extern __shared__ char smem[];
    const uint32_t sb = smem_u32(smem);

    const int tid   = threadIdx.x;
    const int lane  = tid & 31;
    const int warp  = tid >> 5;
    const int warpM = warp & 1;        // 2 warps along M (64 rows)
    const int warpN = warp >> 1;       // 4 warps along N (32 cols)
    const int rowBase = blockIdx.y * BM;
    const int colBase = blockIdx.x * BN;

    const int mrow  = lane & 7;
    const int matLo = (lane >> 3) & 1;
    const int matHi = (lane >> 4) & 1;

    float* aux  = (float*)(smem + OFF_AUX);
    float* c2s  = aux;
    float* s2s  = aux + 128;
    float* rowP = aux + 256;
    float* colP = aux + 384;
    if (tid < 128) {
        c2s[tid] = g_c2[rowBase + tid];
        s2s[tid] = g_s2[colBase + tid];
        rowP[tid] = 0.0f;
        colP[tid] = 0.0f;
    }

    const uint32_t aB[2] = { sb + OFF_A0, sb + OFF_A1 };
    const uint32_t bB[2] = { sb + OFF_B0, sb + OFF_B1 };

    uint32_t acc[4][4][2];   // f16x2 accumulators
#pragma unroll
    for (int mi = 0; mi < 4; mi++)
#pragma unroll
        for (int ni = 0; ni < 4; ni++) { acc[mi][ni][0] = 0u; acc[mi][ni][1] = 0u; }

    auto fill = [&](int buf, int ch) {
#pragma unroll
        for (int t = 0; t < 4; t++) {
            int idx = tid + t * 256;
            int r = idx >> 3, g = idx & 7;
            cp16(aB[buf] + swz((uint32_t)(r * 128 + g * 16)),
                 g_Cb + (size_t)(rowBase + r) * DIM + ch * BKC + g * 8);
        }
#pragma unroll
        for (int t = 0; t < 4; t++) {
            int idx = tid + t * 256;
            int r = idx >> 3, g = idx & 7;
            cp16(bB[buf] + swz((uint32_t)(r * 128 + g * 16)),
                 g_Sb + (size_t)(colBase + r) * DIM + ch * BKC + g * 8);
        }
        asm volatile("cp.async.commit_group;" ::: "memory");
    };

    fill(0, 0);
    fill(1, 1);

    const uint32_t aRowOff = (uint32_t)(warpM * 64 + matLo * 8 + mrow) * 128;
    const uint32_t bRowOff = (uint32_t)(warpN * 32 + matHi * 8 + mrow) * 128;

#pragma unroll
    for (int ch = 0; ch < NCHUNK; ch++) {
        if (ch < NCHUNK - 1) asm volatile("cp.async.wait_group 1;" ::: "memory");
        else                 asm volatile("cp.async.wait_group 0;" ::: "memory");
        __syncthreads();

        const uint32_t ab = aB[ch & 1] + aRowOff;
        const uint32_t bb = bB[ch & 1] + bRowOff;

#pragma unroll
        for (int ks = 0; ks < 4; ks++) {
            const uint32_t ca = (uint32_t)((((ks << 1) | matHi) ^ mrow) << 4);
            const uint32_t cb = (uint32_t)((((ks << 1) | matLo) ^ mrow) << 4);
            uint32_t a[4][4], b[4][2];
#pragma unroll
            for (int mi = 0; mi < 4; mi++)
                ldsm4(a[mi], ab + mi * 2048 + ca);
#pragma unroll
            for (int p = 0; p < 2; p++) {
                uint32_t r[4];
                ldsm4(r, bb + p * 2048 + cb);
                b[2 * p][0] = r[0]; b[2 * p][1] = r[1];
                b[2 * p + 1][0] = r[2]; b[2 * p + 1][1] = r[3];
            }
#pragma unroll
            for (int mi = 0; mi < 4; mi++)
#pragma unroll
                for (int ni = 0; ni < 4; ni++)
                    mma_f16(acc[mi][ni], a[mi], b[ni]);
        }

        if (ch + 2 < NCHUNK) {
            __syncthreads();          // all warps done reading buf (ch&1)
            fill(ch & 1, ch + 2);
        }
    }

    // ---------------- epilogue ----------------
    __syncthreads();

    const float kk = -__expf(T[0]) * LOG2EF;   // e = ex2(dist * kk)
    const bool diagCTA = (blockIdx.x == blockIdx.y);
    const int g   = lane >> 2;
    const int tig = lane & 3;

    float rAcc[8], cAcc[8];
#pragma unroll
    for (int i = 0; i < 8; i++) { rAcc[i] = 0.0f; cAcc[i] = 0.0f; }
    float dloc = 0.0f;

#pragma unroll
    for (int mi = 0; mi < 4; mi++) {
#pragma unroll
        for (int ni = 0; ni < 4; ni++) {
            float2 f01 = __half22float2(*(__half2*)&acc[mi][ni][0]); // row g,   cols 2tig..+1
            float2 f23 = __half22float2(*(__half2*)&acc[mi][ni][1]); // row g+8, cols 2tig..+1
            float accf[4] = { f01.x, f01.y, f23.x, f23.y };
#pragma unroll
            for (int c = 0; c < 4; c++) {
                const int h   = c >> 1;
                const int bb2 = c & 1;
                const int rl = warpM * 64 + mi * 16 + g + h * 8;
                const int cl = warpN * 32 + ni * 8 + tig * 2 + bb2;
                float d2 = fmaxf(fmaf(-2.0f, accf[c], c2s[rl] + s2s[cl]), 0.0f);
                float dist;
                asm("sqrt.approx.f32 %0, %1;" : "=f"(dist) : "f"(d2));
                float f = dist * kk;
                float e;
                asm("ex2.approx.f32 %0, %1;" : "=f"(e) : "f"(f));
                rAcc[mi * 2 + h] += e;
                cAcc[ni * 2 + bb2] += e;
                if (diagCTA && rl == cl) dloc += f;
            }
        }
    }

#pragma unroll
    for (int i = 0; i < 8; i++) {
        float v = rAcc[i];
        v += __shfl_xor_sync(0xffffffffu, v, 1);
        v += __shfl_xor_sync(0xffffffffu, v, 2);
        if (tig == 0) {
            int mi = i >> 1, h = i & 1;
            atomicAdd(&rowP[warpM * 64 + mi * 16 + h * 8 + g], v);
        }
    }
#pragma unroll
    for (int i = 0; i < 8; i++) {
        float v = cAcc[i];
        v += __shfl_xor_sync(0xffffffffu, v, 4);
        v += __shfl_xor_sync(0xffffffffu, v, 8);
        v += __shfl_xor_sync(0xffffffffu, v, 16);
        if (g == 0) {
            int ni = i >> 1, bb2 = i & 1;
            atomicAdd(&colP[warpN * 32 + ni * 8 + tig * 2 + bb2], v);
        }
    }

    if (diagCTA) {
#pragma unroll
        for (int m = 16; m >= 1; m >>= 1)
            dloc += __shfl_xor_sync(0xffffffffu, dloc, m);
        if (lane == 0) atomicAdd(out, -dloc * (LN2F / (float)NPTS));
    }

    __syncthreads();
    if (tid < 128) {
        atomicAdd(&g_rowsum[rowBase + tid], rowP[tid]);
        atomicAdd(&g_colsum[colBase + tid], colP[tid]);
    }
}

// ---------------------------------------------------------------------------
__global__ void dcl_final_kernel(float* __restrict__ out) {
    int i = blockIdx.x * blockDim.x + threadIdx.x;
    float v = logf(g_rowsum[i]) + logf(g_colsum[i]);
#pragma unroll
    for (int m = 16; m >= 1; m >>= 1) v += __shfl_xor_sync(0xffffffffu, v, m);
    if ((threadIdx.x & 31) == 0)
        atomicAdd(out, v * (0.5f / (float)NPTS));
}

// ---------------------------------------------------------------------------
extern "C" void kernel_launch(void* const* d_in, const int* in_sizes, int n_in,
                              void* d_out, int out_size) {
    const float* C = (const float*)d_in[0];
    const float* S = (const float*)d_in[1];
    const float* T = (const float*)d_in[2];
    float* out = (float*)d_out;

    static bool attr_set = false;
    if (!attr_set) {
        cudaFuncSetAttribute(dcl_main_kernel,
                             cudaFuncAttributeMaxDynamicSharedMemorySize, SMEM_TOTAL);
        attr_set = true;
    }

    dcl_prep_kernel<<<NPTS / 8, 256>>>(C, S, out);
    dim3 grid(NPTS / BN, NPTS / BM);
    dcl_main_kernel<<<grid, 256, SMEM_TOTAL>>>(T, out);
    dcl_final_kernel<<<NPTS / 1024, 1024>>>(out);
}